// round 6
// baseline (speedup 1.0000x reference)
#include <cuda_runtime.h>

// Problem-fixed shapes (from reference setup_inputs)
#define BATCH 8192
#define TLEN  256
#define HID   32

// Scratch: decoder pre-gates per batch element (i,f,g,o) — __device__ global, no allocs
__device__ float g_pre[BATCH * 4];

// ---------- helpers ----------
static __device__ __forceinline__ unsigned long long ffma2(unsigned long long a,
                                                           unsigned long long b,
                                                           unsigned long long c) {
    unsigned long long d;
    asm("fma.rn.f32x2 %0, %1, %2, %3;" : "=l"(d) : "l"(a), "l"(b), "l"(c));
    return d;
}
static __device__ __forceinline__ unsigned long long pack2(float lo, float hi) {
    unsigned long long d;
    asm("mov.b64 %0, {%1, %2};" : "=l"(d) : "f"(lo), "f"(hi));
    return d;
}
static __device__ __forceinline__ float hadd2(unsigned long long a) {
    float lo, hi;
    asm("mov.b64 {%0, %1}, %2;" : "=f"(lo), "=f"(hi) : "l"(a));
    return lo + hi;
}
// HW tanh: 1 MUFU op, rel err ~5e-4
static __device__ __forceinline__ float tanhap(float x) {
    float y;
    asm("tanh.approx.f32 %0, %1;" : "=f"(y) : "f"(x));
    return y;
}
// sigmoid(p) where caller supplies p/2 pre-scaled: 0.5 + 0.5*tanh(p/2)
static __device__ __forceinline__ float sig_from_half(float half_p) {
    return fmaf(0.5f, tanhap(half_p), 0.5f);
}

// ---------- encoder: one warp per batch element, lane = hidden unit ----------
__global__ void __launch_bounds__(128, 3) enc_kernel(
    const float* __restrict__ x,        // [B, T, 1]
    const float* __restrict__ eWih,     // [128, 1]
    const float* __restrict__ eWhh,     // [128, 32]
    const float* __restrict__ ebih,     // [128]
    const float* __restrict__ ebhh,     // [128]
    const float* __restrict__ dWih,     // [4, 32]
    const float* __restrict__ dbih,     // [4]
    const float* __restrict__ dbhh)     // [4]
{
    __shared__ __align__(16) float hbuf[4][2][HID];  // 4 warps/block, double-buffered h

    const int lane = threadIdx.x & 31;
    const int w    = threadIdx.x >> 5;
    const int b    = blockIdx.x * 4 + w;

    // Register-resident W_hh rows, as f32x2 pairs. Gates i(0), f(1), o(3) are
    // PRE-SCALED by 0.5 so sigmoid(p) = 0.5 + 0.5*tanh(acc) with no pre-multiply.
    // Gate g(2) stays unscaled (tanh applied directly).
    ulonglong2 wr[4][8];
#pragma unroll
    for (int g = 0; g < 4; g++) {
        const float s = (g == 2) ? 1.0f : 0.5f;
        const float* row = eWhh + (g * HID + lane) * HID;
#pragma unroll
        for (int j = 0; j < 8; j++) {
            wr[g][j].x = pack2(s * row[4 * j + 0], s * row[4 * j + 1]);
            wr[g][j].y = pack2(s * row[4 * j + 2], s * row[4 * j + 3]);
        }
    }

    float bias[4], wx[4];
#pragma unroll
    for (int g = 0; g < 4; g++) {
        const float s = (g == 2) ? 1.0f : 0.5f;
        bias[g] = s * (ebih[g * HID + lane] + ebhh[g * HID + lane]);
        wx[g]   = s * eWih[g * HID + lane];  // IN == 1
    }

    float h = 0.0f, c = 0.0f;
    hbuf[w][0][lane] = 0.0f;
    __syncwarp();

    const float* xs = x + (long)b * TLEN;
    float xl_cur = xs[lane];
    int p = 0;

#pragma unroll 1
    for (int t0 = 0; t0 < TLEN; t0 += 32) {
        float xl_next = (t0 + 32 < TLEN) ? xs[t0 + 32 + lane] : 0.0f;

#pragma unroll 4
        for (int dt = 0; dt < 32; dt++) {
            float xv = __shfl_sync(0xffffffffu, xl_cur, dt);

            unsigned long long ai = pack2(fmaf(xv, wx[0], bias[0]), 0.0f);
            unsigned long long af = pack2(fmaf(xv, wx[1], bias[1]), 0.0f);
            unsigned long long ag = pack2(fmaf(xv, wx[2], bias[2]), 0.0f);
            unsigned long long ao = pack2(fmaf(xv, wx[3], bias[3]), 0.0f);

            const ulonglong2* hb = reinterpret_cast<const ulonglong2*>(hbuf[w][p]);
#pragma unroll
            for (int j = 0; j < 8; j++) {
                ulonglong2 hp = hb[j];   // broadcast LDS.128
                ai = ffma2(wr[0][j].x, hp.x, ai);
                ai = ffma2(wr[0][j].y, hp.y, ai);
                af = ffma2(wr[1][j].x, hp.x, af);
                af = ffma2(wr[1][j].y, hp.y, af);
                ag = ffma2(wr[2][j].x, hp.x, ag);
                ag = ffma2(wr[2][j].y, hp.y, ag);
                ao = ffma2(wr[3][j].x, hp.x, ao);
                ao = ffma2(wr[3][j].y, hp.y, ao);
            }

            // i,f,o accumulators hold p/2 (weights pre-scaled); g holds full p.
            float ig = sig_from_half(hadd2(ai));
            float fg = sig_from_half(hadd2(af));
            float gg = tanhap(hadd2(ag));
            float og = sig_from_half(hadd2(ao));

            c = fmaf(fg, c, ig * gg);
            h = og * tanhap(c);

            hbuf[w][p ^ 1][lane] = h;
            __syncwarp();
            p ^= 1;
        }
        xl_cur = xl_next;
    }

    // Decoder pre-gates: pre[j] = h . dec_W_ih[j] + dec_b_ih[j] + dec_b_hh[j]
    float v0 = h * dWih[0 * HID + lane];
    float v1 = h * dWih[1 * HID + lane];
    float v2 = h * dWih[2 * HID + lane];
    float v3 = h * dWih[3 * HID + lane];
#pragma unroll
    for (int off = 16; off >= 1; off >>= 1) {
        v0 += __shfl_xor_sync(0xffffffffu, v0, off);
        v1 += __shfl_xor_sync(0xffffffffu, v1, off);
        v2 += __shfl_xor_sync(0xffffffffu, v2, off);
        v3 += __shfl_xor_sync(0xffffffffu, v3, off);
    }
    if (lane == 0) {
        float4 r;
        r.x = v0 + dbih[0] + dbhh[0];
        r.y = v1 + dbih[1] + dbhh[1];
        r.z = v2 + dbih[2] + dbhh[2];
        r.w = v3 + dbih[3] + dbhh[3];
        reinterpret_cast<float4*>(g_pre)[b] = r;
    }
}

// ---------- decoder: one thread per batch element, scalar recurrence ----------
// Latency-bound serial chain: shorten it with HW tanh (chain ~52 cyc/step vs ~100).
__global__ void __launch_bounds__(64) dec_kernel(
    const float* __restrict__ dWhh,   // [4, 1]
    float* __restrict__ out)          // [B, T, 1]
{
    const int b = blockIdx.x * blockDim.x + threadIdx.x;
    if (b >= BATCH) return;

    const float4 pre = reinterpret_cast<const float4*>(g_pre)[b];
    // Pre-scale i,f,o paths by 0.5 for the tanh-identity sigmoid.
    const float pxi = 0.5f * pre.x, pxf = 0.5f * pre.y, pxo = 0.5f * pre.w;
    const float wi = 0.5f * dWhh[0], wf = 0.5f * dWhh[1];
    const float wg = dWhh[2],        wo = 0.5f * dWhh[3];
    const float pxg = pre.z;

    float h = 0.0f, c = 0.0f;
    float4* outv = reinterpret_cast<float4*>(out + (long)b * TLEN);

#pragma unroll 1
    for (int t = 0; t < TLEN; t += 4) {
        float4 ov;
        float* op = &ov.x;
#pragma unroll
        for (int k = 0; k < 4; k++) {
            float ig = sig_from_half(fmaf(wi, h, pxi));
            float fg = sig_from_half(fmaf(wf, h, pxf));
            float gg = tanhap(fmaf(wg, h, pxg));
            float og = sig_from_half(fmaf(wo, h, pxo));
            c = fmaf(fg, c, ig * gg);
            h = og * tanhap(c);
            op[k] = h;
        }
        outv[t >> 2] = ov;
    }
}

// ---------- launch ----------
extern "C" void kernel_launch(void* const* d_in, const int* in_sizes, int n_in,
                              void* d_out, int out_size) {
    const float* x     = (const float*)d_in[0];
    const float* eWih  = (const float*)d_in[1];
    const float* eWhh  = (const float*)d_in[2];
    const float* ebih  = (const float*)d_in[3];
    const float* ebhh  = (const float*)d_in[4];
    const float* dWih  = (const float*)d_in[5];
    const float* dWhh  = (const float*)d_in[6];
    const float* dbih  = (const float*)d_in[7];
    const float* dbhh  = (const float*)d_in[8];
    float* out = (float*)d_out;

    enc_kernel<<<BATCH / 4, 128>>>(x, eWih, eWhh, ebih, ebhh, dWih, dbih, dbhh);
    dec_kernel<<<BATCH / 64, 64>>>(dWhh, out);
}

// round 11
// speedup vs baseline: 1.9302x; 1.9302x over previous
#include <cuda_runtime.h>

// Problem-fixed shapes (from reference setup_inputs)
#define BATCH 8192
#define TLEN  256
#define HID   32

// Scratch: decoder pre-gates per batch element (i,f,g,o) — __device__ global, no allocs
__device__ float g_pre[BATCH * 4];

// ---------- helpers ----------
static __device__ __forceinline__ unsigned long long ffma2(unsigned long long a,
                                                           unsigned long long b,
                                                           unsigned long long c) {
    unsigned long long d;
    asm("fma.rn.f32x2 %0, %1, %2, %3;" : "=l"(d) : "l"(a), "l"(b), "l"(c));
    return d;
}
static __device__ __forceinline__ unsigned long long pack2(float lo, float hi) {
    unsigned long long d;
    asm("mov.b64 %0, {%1, %2};" : "=l"(d) : "f"(lo), "f"(hi));
    return d;
}
static __device__ __forceinline__ float hadd2(unsigned long long a) {
    float lo, hi;
    asm("mov.b64 {%0, %1}, %2;" : "=f"(lo), "=f"(hi) : "l"(a));
    return lo + hi;
}
// HW tanh: 1 MUFU op, rel err ~5e-4
static __device__ __forceinline__ float tanhap(float x) {
    float y;
    asm("tanh.approx.f32 %0, %1;" : "=f"(y) : "f"(x));
    return y;
}
// sigmoid(p) = 0.5 + 0.5*tanh(0.5*p): FMUL + MUFU.TANH + FMA
static __device__ __forceinline__ float sigmoid_t(float p) {
    return fmaf(0.5f, tanhap(0.5f * p), 0.5f);
}
// sigmoid from pre-halved argument (decoder folds the 0.5 into constants)
static __device__ __forceinline__ float sig_from_half(float half_p) {
    return fmaf(0.5f, tanhap(half_p), 0.5f);
}

// ---------- encoder: one warp per batch element, lane = hidden unit ----------
// Weight-load prologue kept byte-identical to the R5 kernel (vector ulonglong2
// loads, NO per-element scaling) — scalar-load + pack variants push ptxas past
// the 168-reg cap and spill the 128 weight regs into the hot loop (R6 regression).
__global__ void __launch_bounds__(128, 3) enc_kernel(
    const float* __restrict__ x,        // [B, T, 1]
    const float* __restrict__ eWih,     // [128, 1]
    const float* __restrict__ eWhh,     // [128, 32]
    const float* __restrict__ ebih,     // [128]
    const float* __restrict__ ebhh,     // [128]
    const float* __restrict__ dWih,     // [4, 32]
    const float* __restrict__ dbih,     // [4]
    const float* __restrict__ dbhh)     // [4]
{
    __shared__ __align__(16) float hbuf[4][2][HID];  // 4 warps/block, double-buffered h

    const int lane = threadIdx.x & 31;
    const int w    = threadIdx.x >> 5;
    const int b    = blockIdx.x * 4 + w;

    // Register-resident W_hh rows for this lane's hidden unit, as f32x2 pairs.
    ulonglong2 wr[4][8];
#pragma unroll
    for (int g = 0; g < 4; g++) {
        const ulonglong2* row = reinterpret_cast<const ulonglong2*>(eWhh + (g * HID + lane) * HID);
#pragma unroll
        for (int j = 0; j < 8; j++) wr[g][j] = row[j];
    }

    float bias[4], wx[4];
#pragma unroll
    for (int g = 0; g < 4; g++) {
        bias[g] = ebih[g * HID + lane] + ebhh[g * HID + lane];
        wx[g]   = eWih[g * HID + lane];  // IN == 1
    }

    float h = 0.0f, c = 0.0f;
    hbuf[w][0][lane] = 0.0f;
    __syncwarp();

    const float* xs = x + (long)b * TLEN;
    float xl_cur = xs[lane];
    int p = 0;

#pragma unroll 1
    for (int t0 = 0; t0 < TLEN; t0 += 32) {
        float xl_next = (t0 + 32 < TLEN) ? xs[t0 + 32 + lane] : 0.0f;

#pragma unroll 4
        for (int dt = 0; dt < 32; dt++) {
            float xv = __shfl_sync(0xffffffffu, xl_cur, dt);

            unsigned long long ai = pack2(fmaf(xv, wx[0], bias[0]), 0.0f);
            unsigned long long af = pack2(fmaf(xv, wx[1], bias[1]), 0.0f);
            unsigned long long ag = pack2(fmaf(xv, wx[2], bias[2]), 0.0f);
            unsigned long long ao = pack2(fmaf(xv, wx[3], bias[3]), 0.0f);

            const ulonglong2* hb = reinterpret_cast<const ulonglong2*>(hbuf[w][p]);
#pragma unroll
            for (int j = 0; j < 8; j++) {
                ulonglong2 hp = hb[j];   // broadcast LDS.128
                ai = ffma2(wr[0][j].x, hp.x, ai);
                ai = ffma2(wr[0][j].y, hp.y, ai);
                af = ffma2(wr[1][j].x, hp.x, af);
                af = ffma2(wr[1][j].y, hp.y, af);
                ag = ffma2(wr[2][j].x, hp.x, ag);
                ag = ffma2(wr[2][j].y, hp.y, ag);
                ao = ffma2(wr[3][j].x, hp.x, ao);
                ao = ffma2(wr[3][j].y, hp.y, ao);
            }

            float ig = sigmoid_t(hadd2(ai));
            float fg = sigmoid_t(hadd2(af));
            float gg = tanhap(hadd2(ag));
            float og = sigmoid_t(hadd2(ao));

            c = fmaf(fg, c, ig * gg);
            h = og * tanhap(c);

            hbuf[w][p ^ 1][lane] = h;
            __syncwarp();
            p ^= 1;
        }
        xl_cur = xl_next;
    }

    // Decoder pre-gates: pre[j] = h . dec_W_ih[j] + dec_b_ih[j] + dec_b_hh[j]
    float v0 = h * dWih[0 * HID + lane];
    float v1 = h * dWih[1 * HID + lane];
    float v2 = h * dWih[2 * HID + lane];
    float v3 = h * dWih[3 * HID + lane];
#pragma unroll
    for (int off = 16; off >= 1; off >>= 1) {
        v0 += __shfl_xor_sync(0xffffffffu, v0, off);
        v1 += __shfl_xor_sync(0xffffffffu, v1, off);
        v2 += __shfl_xor_sync(0xffffffffu, v2, off);
        v3 += __shfl_xor_sync(0xffffffffu, v3, off);
    }
    if (lane == 0) {
        float4 r;
        r.x = v0 + dbih[0] + dbhh[0];
        r.y = v1 + dbih[1] + dbhh[1];
        r.z = v2 + dbih[2] + dbhh[2];
        r.w = v3 + dbih[3] + dbhh[3];
        reinterpret_cast<float4*>(g_pre)[b] = r;
    }
}

// ---------- decoder: one thread per batch element, scalar recurrence ----------
// R6-measured version (21.0us): HW tanh shortens the serial chain; constants
// pre-halved for the tanh-identity sigmoid.
__global__ void __launch_bounds__(64) dec_kernel(
    const float* __restrict__ dWhh,   // [4, 1]
    float* __restrict__ out)          // [B, T, 1]
{
    const int b = blockIdx.x * blockDim.x + threadIdx.x;
    if (b >= BATCH) return;

    const float4 pre = reinterpret_cast<const float4*>(g_pre)[b];
    const float pxi = 0.5f * pre.x, pxf = 0.5f * pre.y, pxo = 0.5f * pre.w;
    const float wi = 0.5f * dWhh[0], wf = 0.5f * dWhh[1];
    const float wg = dWhh[2],        wo = 0.5f * dWhh[3];
    const float pxg = pre.z;

    float h = 0.0f, c = 0.0f;
    float4* outv = reinterpret_cast<float4*>(out + (long)b * TLEN);

#pragma unroll 1
    for (int t = 0; t < TLEN; t += 4) {
        float4 ov;
        float* op = &ov.x;
#pragma unroll
        for (int k = 0; k < 4; k++) {
            float ig = sig_from_half(fmaf(wi, h, pxi));
            float fg = sig_from_half(fmaf(wf, h, pxf));
            float gg = tanhap(fmaf(wg, h, pxg));
            float og = sig_from_half(fmaf(wo, h, pxo));
            c = fmaf(fg, c, ig * gg);
            h = og * tanhap(c);
            op[k] = h;
        }
        outv[t >> 2] = ov;
    }
}

// ---------- launch ----------
extern "C" void kernel_launch(void* const* d_in, const int* in_sizes, int n_in,
                              void* d_out, int out_size) {
    const float* x     = (const float*)d_in[0];
    const float* eWih  = (const float*)d_in[1];
    const float* eWhh  = (const float*)d_in[2];
    const float* ebih  = (const float*)d_in[3];
    const float* ebhh  = (const float*)d_in[4];
    const float* dWih  = (const float*)d_in[5];
    const float* dWhh  = (const float*)d_in[6];
    const float* dbih  = (const float*)d_in[7];
    const float* dbhh  = (const float*)d_in[8];
    float* out = (float*)d_out;

    enc_kernel<<<BATCH / 4, 128>>>(x, eWih, eWhh, ebih, ebhh, dWih, dbih, dbhh);
    dec_kernel<<<BATCH / 64, 64>>>(dWhh, out);
}